// round 3
// baseline (speedup 1.0000x reference)
#include <cuda_runtime.h>
#include <math_constants.h>

#define N_NODES 50000
#define N_EDGES 800000
#define IN_F 128
#define HF    128   // HEADS * OUT_F
#define HEADS 4
#define NEG_SLOPE 0.2f
#define EPSF 1e-8f

// ---------------- scratch (static device globals; no allocations) -------------
__device__ __align__(16) float g_h[N_NODES * HF];        // 25.6 MB
__device__ float  g_Wt[IN_F * HF];                        // W transposed (k-major)
__device__ __align__(16) float g_asrc[N_NODES * HEADS];   // per-node alpha_src
__device__ __align__(16) float g_adst[N_NODES * HEADS];
__device__ __align__(16) float g_m[N_NODES * HEADS];      // segment max
__device__ __align__(16) float g_s[N_NODES * HEADS];      // segment sum of exp
__device__ float4 g_exp[N_EDGES];                         // per-edge exp (12.8 MB)
__device__ __align__(8) int2 g_edges[N_EDGES];            // packed (src,dst) 6.4 MB
__device__ int g_is64;                                    // dtype flag

// ---------------- helpers -----------------------------------------------------
__device__ __forceinline__ void atomicMaxF(float* a, float v) {
    if (v >= 0.f) atomicMax((int*)a, __float_as_int(v));
    else          atomicMin((unsigned int*)a, __float_as_uint(v));
}

__device__ __forceinline__ void redAddV4(float* p, float a, float b, float c, float d) {
    asm volatile("red.global.add.v4.f32 [%0], {%1,%2,%3,%4};"
                 :: "l"(p), "f"(a), "f"(b), "f"(c), "f"(d) : "memory");
}

__device__ __forceinline__ int clampN(int v) {
    v = v < 0 ? 0 : v;
    return v >= N_NODES ? N_NODES - 1 : v;
}

// ---------------- kernel 0: detect edge_index dtype ---------------------------
// int64 values are all < 50000 -> high 32 bits of every 8-byte word are 0.
// int32 data reinterpreted as int64 puts a uniform index in the high word.
__global__ void k_detect(const void* __restrict__ ei) {
    if (threadIdx.x == 0 && blockIdx.x == 0) {
        const long long* p = (const long long*)ei;
        int is64 = 1;
        for (int i = 0; i < 128; ++i) {
            if ((unsigned long long)p[i] >> 32) { is64 = 0; break; }
        }
        g_is64 = is64;
    }
}

// ---------------- kernel 0b: pack edges to int2 --------------------------------
__global__ void k_pack(const void* __restrict__ ei) {
    int e = blockIdx.x * 256 + threadIdx.x;
    if (e >= N_EDGES) return;
    int src, dst;
    if (g_is64) {
        src = (int)((const long long*)ei)[e];
        dst = (int)((const long long*)ei)[N_EDGES + e];
    } else {
        src = ((const int*)ei)[e];
        dst = ((const int*)ei)[N_EDGES + e];
    }
    g_edges[e] = make_int2(clampN(src), clampN(dst));
}

// ---------------- kernel 1: transpose W --------------------------------------
__global__ void k_transpose(const float* __restrict__ W) {
    int i = blockIdx.x * 256 + threadIdx.x;
    if (i < HF * IN_F) {
        int j = i / IN_F, k = i % IN_F;
        g_Wt[k * HF + j] = W[i];
    }
}

// ---------------- kernel 2: init out / m / s ----------------------------------
__global__ void k_init(float* __restrict__ out) {
    int i = blockIdx.x * 256 + threadIdx.x;
    if (i < N_NODES * HF) out[i] = 0.f;
    if (i < N_NODES * HEADS) {
        g_m[i] = -CUDART_INF_F;
        g_s[i] = 0.f;
    }
}

// ---------------- kernel 3: h = x @ W^T  + alpha epilogue ---------------------
__global__ void __launch_bounds__(256) k_gemm(const float* __restrict__ x,
                                              const float* __restrict__ a_src,
                                              const float* __restrict__ a_dst) {
    __shared__ float xsT[IN_F][65];   // k-major x tile (padded)
    __shared__ float sA[HF], sB[HF];

    int tid = threadIdx.x;
    if (tid < HF) { sA[tid] = a_src[tid]; sB[tid] = a_dst[tid]; }

    int n0 = blockIdx.x * 64;

    #pragma unroll
    for (int it = 0; it < 8; ++it) {
        int flat = tid + it * 256;          // float4 index, 2048 total
        int n  = flat >> 5;                 // 0..63 (32 float4 per row)
        int kq = flat & 31;
        float4 v = make_float4(0.f, 0.f, 0.f, 0.f);
        int gn = n0 + n;
        if (gn < N_NODES) v = *(const float4*)&x[(size_t)gn * IN_F + kq * 4];
        xsT[kq * 4 + 0][n] = v.x;
        xsT[kq * 4 + 1][n] = v.y;
        xsT[kq * 4 + 2][n] = v.z;
        xsT[kq * 4 + 3][n] = v.w;
    }
    __syncthreads();

    int jq = tid & 31;  int j0 = jq * 4;
    int ng = tid >> 5;  int nb = ng * 8;

    float4 acc[8];
    #pragma unroll
    for (int i = 0; i < 8; ++i) acc[i] = make_float4(0.f, 0.f, 0.f, 0.f);

    #pragma unroll 4
    for (int k = 0; k < IN_F; ++k) {
        float4 wv = *(const float4*)&g_Wt[k * HF + j0];  // coalesced, L1-hit
        #pragma unroll
        for (int i = 0; i < 8; ++i) {
            float xv = xsT[k][nb + i];                   // broadcast LDS
            acc[i].x += wv.x * xv;
            acc[i].y += wv.y * xv;
            acc[i].z += wv.z * xv;
            acc[i].w += wv.w * xv;
        }
    }

    int head = jq >> 3;
    #pragma unroll
    for (int i = 0; i < 8; ++i) {
        int gn = n0 + nb + i;
        bool ok = gn < N_NODES;
        if (ok) *(float4*)&g_h[(size_t)gn * HF + j0] = acc[i];
        float s1 = acc[i].x * sA[j0] + acc[i].y * sA[j0 + 1] +
                   acc[i].z * sA[j0 + 2] + acc[i].w * sA[j0 + 3];
        float s2 = acc[i].x * sB[j0] + acc[i].y * sB[j0 + 1] +
                   acc[i].z * sB[j0 + 2] + acc[i].w * sB[j0 + 3];
        #pragma unroll
        for (int off = 1; off < 8; off <<= 1) {
            s1 += __shfl_xor_sync(0xffffffffu, s1, off);
            s2 += __shfl_xor_sync(0xffffffffu, s2, off);
        }
        if (ok && (jq & 7) == 0) {
            g_asrc[gn * HEADS + head] = s1;
            g_adst[gn * HEADS + head] = s2;
        }
    }
}

// ---------------- kernel 4: per-edge logits + segment max ---------------------
__global__ void k_edge_max() {
    int e = blockIdx.x * 256 + threadIdx.x;
    if (e >= N_EDGES) return;
    int2 ed = g_edges[e];
    float4 a = *(const float4*)&g_asrc[ed.x * HEADS];
    float4 b = *(const float4*)&g_adst[ed.y * HEADS];
    float v0 = a.x + b.x, v1 = a.y + b.y, v2 = a.z + b.z, v3 = a.w + b.w;
    v0 = v0 > 0.f ? v0 : NEG_SLOPE * v0;
    v1 = v1 > 0.f ? v1 : NEG_SLOPE * v1;
    v2 = v2 > 0.f ? v2 : NEG_SLOPE * v2;
    v3 = v3 > 0.f ? v3 : NEG_SLOPE * v3;
    float* m = &g_m[ed.y * HEADS];
    atomicMaxF(m + 0, v0);
    atomicMaxF(m + 1, v1);
    atomicMaxF(m + 2, v2);
    atomicMaxF(m + 3, v3);
}

// ---------------- kernel 5: exp + segment sum ---------------------------------
__global__ void k_edge_exp() {
    int e = blockIdx.x * 256 + threadIdx.x;
    if (e >= N_EDGES) return;
    int2 ed = g_edges[e];
    float4 a = *(const float4*)&g_asrc[ed.x * HEADS];
    float4 b = *(const float4*)&g_adst[ed.y * HEADS];
    float v0 = a.x + b.x, v1 = a.y + b.y, v2 = a.z + b.z, v3 = a.w + b.w;
    v0 = v0 > 0.f ? v0 : NEG_SLOPE * v0;
    v1 = v1 > 0.f ? v1 : NEG_SLOPE * v1;
    v2 = v2 > 0.f ? v2 : NEG_SLOPE * v2;
    v3 = v3 > 0.f ? v3 : NEG_SLOPE * v3;
    float4 m = *(const float4*)&g_m[ed.y * HEADS];
    float e0 = __expf(v0 - m.x);
    float e1 = __expf(v1 - m.y);
    float e2 = __expf(v2 - m.z);
    float e3 = __expf(v3 - m.w);
    g_exp[e] = make_float4(e0, e1, e2, e3);
    redAddV4(&g_s[ed.y * HEADS], e0, e1, e2, e3);
}

// ---------------- kernel 6: weighted scatter-add aggregation ------------------
// one warp per edge; lane l handles feature quad j = 4*l (head = l>>3)
__global__ void __launch_bounds__(256) k_agg(float* __restrict__ out) {
    int warp = (blockIdx.x * 256 + threadIdx.x) >> 5;
    int lane = threadIdx.x & 31;
    if (warp >= N_EDGES) return;
    int2 ed = g_edges[warp];
    int head = lane >> 3;
    float expv = ((const float*)&g_exp[warp])[head];
    float sv   = g_s[ed.y * HEADS + head];
    float att  = expv / (sv + EPSF);
    float4 hv = *(const float4*)&g_h[(size_t)ed.x * HF + lane * 4];
    redAddV4(&out[(size_t)ed.y * HF + lane * 4],
             hv.x * att, hv.y * att, hv.z * att, hv.w * att);
}

// ---------------- launch ------------------------------------------------------
extern "C" void kernel_launch(void* const* d_in, const int* in_sizes, int n_in,
                              void* d_out, int out_size) {
    const float* x     = (const float*)d_in[0];
    const void*  ei    = d_in[1];
    const float* W     = (const float*)d_in[2];
    const float* a_src = (const float*)d_in[3];
    const float* a_dst = (const float*)d_in[4];
    float*       out   = (float*)d_out;

    k_detect<<<1, 32>>>(ei);
    k_pack<<<(N_EDGES + 255) / 256, 256>>>(ei);
    k_transpose<<<(HF * IN_F + 255) / 256, 256>>>(W);
    k_init<<<(N_NODES * HF + 255) / 256, 256>>>(out);
    k_gemm<<<(N_NODES + 63) / 64, 256>>>(x, a_src, a_dst);
    k_edge_max<<<(N_EDGES + 255) / 256, 256>>>();
    k_edge_exp<<<(N_EDGES + 255) / 256, 256>>>();
    k_agg<<<(N_EDGES * 32 + 255) / 256, 256>>>(out);
}

// round 4
// speedup vs baseline: 1.3118x; 1.3118x over previous
#include <cuda_runtime.h>
#include <math_constants.h>

#define N_NODES 50000
#define N_EDGES 800000
#define IN_F 128
#define HF    128   // HEADS * OUT_F
#define HEADS 4
#define NEG_SLOPE 0.2f
#define EPSF 1e-8f

// ---------------- scratch (static device globals; no allocations) -------------
__device__ __align__(16) float g_h[N_NODES * HF];        // 25.6 MB
__device__ float  g_Wt[IN_F * HF];                        // W transposed (k-major)
__device__ __align__(16) float g_asrc[N_NODES * HEADS];   // per-node alpha_src
__device__ __align__(16) float g_adst[N_NODES * HEADS];
__device__ __align__(8) int2 g_edges[N_EDGES];            // packed (src,dst)
__device__ int  g_cnt[N_NODES];                           // per-dst degree
__device__ int  g_fill[N_NODES];                          // scatter cursors
__device__ int  g_off[N_NODES + 1];                       // CSR offsets
__device__ int  g_csr_src[N_EDGES];                       // src sorted by dst
__device__ int  g_is64;                                   // dtype flag

__device__ __forceinline__ int clampN(int v) {
    v = v < 0 ? 0 : v;
    return v >= N_NODES ? N_NODES - 1 : v;
}

// ---------------- kernel 0: detect edge_index dtype ---------------------------
__global__ void k_detect(const void* __restrict__ ei) {
    if (threadIdx.x == 0 && blockIdx.x == 0) {
        const long long* p = (const long long*)ei;
        int is64 = 1;
        for (int i = 0; i < 128; ++i) {
            if ((unsigned long long)p[i] >> 32) { is64 = 0; break; }
        }
        g_is64 = is64;
    }
}

// ---------------- kernel 0a: zero counters ------------------------------------
__global__ void k_zero() {
    int i = blockIdx.x * 256 + threadIdx.x;
    if (i < N_NODES) { g_cnt[i] = 0; g_fill[i] = 0; }
}

// ---------------- kernel 0b: pack edges + histogram dst -----------------------
__global__ void k_pack(const void* __restrict__ ei) {
    int e = blockIdx.x * 256 + threadIdx.x;
    if (e >= N_EDGES) return;
    int src, dst;
    if (g_is64) {
        src = (int)((const long long*)ei)[e];
        dst = (int)((const long long*)ei)[N_EDGES + e];
    } else {
        src = ((const int*)ei)[e];
        dst = ((const int*)ei)[N_EDGES + e];
    }
    src = clampN(src); dst = clampN(dst);
    g_edges[e] = make_int2(src, dst);
    atomicAdd(&g_cnt[dst], 1);
}

// ---------------- kernel 0c: exclusive scan (single block) --------------------
__global__ void __launch_bounds__(1024) k_scan() {
    __shared__ int partial[1024];
    const int CH = (N_NODES + 1023) / 1024;     // 49
    int t = threadIdx.x;
    int lo = t * CH, hi = min(lo + CH, N_NODES);
    int s = 0;
    for (int i = lo; i < hi; ++i) s += g_cnt[i];
    partial[t] = s;
    __syncthreads();
    // inclusive Hillis-Steele
    for (int off = 1; off < 1024; off <<= 1) {
        int v = (t >= off) ? partial[t - off] : 0;
        __syncthreads();
        partial[t] += v;
        __syncthreads();
    }
    int run = t ? partial[t - 1] : 0;           // exclusive base
    for (int i = lo; i < hi; ++i) { g_off[i] = run; run += g_cnt[i]; }
    if (t == 0) g_off[N_NODES] = N_EDGES;
}

// ---------------- kernel 0d: scatter src into CSR slots ------------------------
__global__ void k_scatter() {
    int e = blockIdx.x * 256 + threadIdx.x;
    if (e >= N_EDGES) return;
    int2 ed = g_edges[e];
    int pos = g_off[ed.y] + atomicAdd(&g_fill[ed.y], 1);
    g_csr_src[pos] = ed.x;
}

// ---------------- kernel 1: transpose W ---------------------------------------
__global__ void k_transpose(const float* __restrict__ W) {
    int i = blockIdx.x * 256 + threadIdx.x;
    if (i < HF * IN_F) {
        int j = i / IN_F, k = i % IN_F;
        g_Wt[k * HF + j] = W[i];
    }
}

// ---------------- kernel 2: h = x @ W^T  + alpha epilogue ----------------------
__global__ void __launch_bounds__(256) k_gemm(const float* __restrict__ x,
                                              const float* __restrict__ a_src,
                                              const float* __restrict__ a_dst) {
    __shared__ float xsT[IN_F][65];
    __shared__ float sA[HF], sB[HF];

    int tid = threadIdx.x;
    if (tid < HF) { sA[tid] = a_src[tid]; sB[tid] = a_dst[tid]; }

    int n0 = blockIdx.x * 64;

    #pragma unroll
    for (int it = 0; it < 8; ++it) {
        int flat = tid + it * 256;
        int n  = flat >> 5;
        int kq = flat & 31;
        float4 v = make_float4(0.f, 0.f, 0.f, 0.f);
        int gn = n0 + n;
        if (gn < N_NODES) v = *(const float4*)&x[(size_t)gn * IN_F + kq * 4];
        xsT[kq * 4 + 0][n] = v.x;
        xsT[kq * 4 + 1][n] = v.y;
        xsT[kq * 4 + 2][n] = v.z;
        xsT[kq * 4 + 3][n] = v.w;
    }
    __syncthreads();

    int jq = tid & 31;  int j0 = jq * 4;
    int ng = tid >> 5;  int nb = ng * 8;

    float4 acc[8];
    #pragma unroll
    for (int i = 0; i < 8; ++i) acc[i] = make_float4(0.f, 0.f, 0.f, 0.f);

    #pragma unroll 4
    for (int k = 0; k < IN_F; ++k) {
        float4 wv = *(const float4*)&g_Wt[k * HF + j0];
        #pragma unroll
        for (int i = 0; i < 8; ++i) {
            float xv = xsT[k][nb + i];
            acc[i].x += wv.x * xv;
            acc[i].y += wv.y * xv;
            acc[i].z += wv.z * xv;
            acc[i].w += wv.w * xv;
        }
    }

    int head = jq >> 3;
    #pragma unroll
    for (int i = 0; i < 8; ++i) {
        int gn = n0 + nb + i;
        bool ok = gn < N_NODES;
        if (ok) *(float4*)&g_h[(size_t)gn * HF + j0] = acc[i];
        float s1 = acc[i].x * sA[j0] + acc[i].y * sA[j0 + 1] +
                   acc[i].z * sA[j0 + 2] + acc[i].w * sA[j0 + 3];
        float s2 = acc[i].x * sB[j0] + acc[i].y * sB[j0 + 1] +
                   acc[i].z * sB[j0 + 2] + acc[i].w * sB[j0 + 3];
        #pragma unroll
        for (int off = 1; off < 8; off <<= 1) {
            s1 += __shfl_xor_sync(0xffffffffu, s1, off);
            s2 += __shfl_xor_sync(0xffffffffu, s2, off);
        }
        if (ok && (jq & 7) == 0) {
            g_asrc[gn * HEADS + head] = s1;
            g_adst[gn * HEADS + head] = s2;
        }
    }
}

// ---------------- kernel 3: CSR aggregation (warp per dst node) ----------------
// For node n: out[n] = (sum_e exp(leaky(asrc[src_e]+adst[n])) * h[src_e]) / (sum_e exp + eps)
// Max-subtraction omitted: it cancels exactly in the ratio; logits are O(1).
#define CHUNK 64
__global__ void __launch_bounds__(256) k_agg(float* __restrict__ out) {
    __shared__ float4 sh_exp[8][CHUNK];
    __shared__ int    sh_src[8][CHUNK];

    int w    = threadIdx.x >> 5;                 // warp in block
    int lane = threadIdx.x & 31;
    int n    = blockIdx.x * 8 + w;               // dst node
    if (n >= N_NODES) return;

    int start = g_off[n];
    int end   = g_off[n + 1];

    float4 acc = make_float4(0.f, 0.f, 0.f, 0.f);
    float4 sum = make_float4(0.f, 0.f, 0.f, 0.f);
    int head = lane >> 3;

    if (start < end) {
        float4 b4 = *(const float4*)&g_adst[n * HEADS];

        for (int cs = start; cs < end; cs += CHUNK) {
            int cnt = min(end - cs, CHUNK);
            // phase A: lane-parallel exp of logits
            for (int k = lane; k < cnt; k += 32) {
                int src = g_csr_src[cs + k];
                float4 a = *(const float4*)&g_asrc[src * HEADS];
                float v0 = a.x + b4.x, v1 = a.y + b4.y;
                float v2 = a.z + b4.z, v3 = a.w + b4.w;
                v0 = v0 > 0.f ? v0 : NEG_SLOPE * v0;
                v1 = v1 > 0.f ? v1 : NEG_SLOPE * v1;
                v2 = v2 > 0.f ? v2 : NEG_SLOPE * v2;
                v3 = v3 > 0.f ? v3 : NEG_SLOPE * v3;
                float4 ex = make_float4(__expf(v0), __expf(v1), __expf(v2), __expf(v3));
                sh_exp[w][k] = ex;
                sh_src[w][k] = src;
                sum.x += ex.x; sum.y += ex.y; sum.z += ex.z; sum.w += ex.w;
            }
            __syncwarp();
            // phase B: serial over edges, lanes cover 128 features
            #pragma unroll 4
            for (int k = 0; k < cnt; ++k) {
                int src = sh_src[w][k];
                float att = ((const float*)&sh_exp[w][k])[head];
                float4 hv = *(const float4*)&g_h[(size_t)src * HF + lane * 4];
                acc.x += att * hv.x;
                acc.y += att * hv.y;
                acc.z += att * hv.z;
                acc.w += att * hv.w;
            }
            __syncwarp();
        }

        // warp-reduce the per-lane partial sums of exp
        #pragma unroll
        for (int off = 1; off < 32; off <<= 1) {
            sum.x += __shfl_xor_sync(0xffffffffu, sum.x, off);
            sum.y += __shfl_xor_sync(0xffffffffu, sum.y, off);
            sum.z += __shfl_xor_sync(0xffffffffu, sum.z, off);
            sum.w += __shfl_xor_sync(0xffffffffu, sum.w, off);
        }
        float sh = ((const float*)&sum)[head];
        float inv = 1.f / (sh + EPSF);
        acc.x *= inv; acc.y *= inv; acc.z *= inv; acc.w *= inv;
    }
    // write full row (zeros for empty segments)
    *(float4*)&out[(size_t)n * HF + lane * 4] = acc;
}

// ---------------- launch -------------------------------------------------------
extern "C" void kernel_launch(void* const* d_in, const int* in_sizes, int n_in,
                              void* d_out, int out_size) {
    const float* x     = (const float*)d_in[0];
    const void*  ei    = d_in[1];
    const float* W     = (const float*)d_in[2];
    const float* a_src = (const float*)d_in[3];
    const float* a_dst = (const float*)d_in[4];
    float*       out   = (float*)d_out;

    k_detect<<<1, 32>>>(ei);
    k_zero<<<(N_NODES + 255) / 256, 256>>>();
    k_pack<<<(N_EDGES + 255) / 256, 256>>>(ei);
    k_scan<<<1, 1024>>>();
    k_scatter<<<(N_EDGES + 255) / 256, 256>>>();
    k_transpose<<<(HF * IN_F + 255) / 256, 256>>>(W);
    k_gemm<<<(N_NODES + 63) / 64, 256>>>(x, a_src, a_dst);
    k_agg<<<(N_NODES + 7) / 8, 256>>>(out);
}

// round 7
// speedup vs baseline: 1.7153x; 1.3076x over previous
#include <cuda_runtime.h>
#include <math_constants.h>

#define N_NODES 50000
#define N_EDGES 800000
#define IN_F 128
#define HF    128   // HEADS * OUT_F
#define HEADS 4
#define NEG_SLOPE 0.2f
#define EPSF 1e-8f

#define SCAN_B 1024
#define N_SCAN_BLOCKS ((N_NODES + SCAN_B - 1) / SCAN_B)   // 49

// ---------------- scratch (static device globals; no allocations) -------------
__device__ __align__(16) float g_h[N_NODES * HF];        // 25.6 MB
__device__ float  g_Wt[IN_F * HF];                        // W transposed (k-major)
__device__ __align__(16) float g_asrc[N_NODES * HEADS];
__device__ __align__(16) float g_adst[N_NODES * HEADS];
__device__ __align__(8) int2 g_edges[N_EDGES];            // packed (src,dst)
__device__ int  g_cnt[N_NODES];                           // per-dst degree
__device__ int  g_fill[N_NODES];                          // scatter cursors
__device__ int  g_off[N_NODES + 1];                       // CSR offsets
__device__ int  g_bsum[N_SCAN_BLOCKS];                    // per-block totals
__device__ int  g_csr_src[N_EDGES];                       // src sorted by dst
__device__ int  g_is64;                                   // dtype flag

__device__ __forceinline__ int clampN(int v) {
    v = v < 0 ? 0 : v;
    return v >= N_NODES ? N_NODES - 1 : v;
}

// ---------------- kernel 0: detect edge_index dtype (1 warp, parallel) --------
__global__ void k_detect(const void* __restrict__ ei) {
    const long long* p = (const long long*)ei;
    int lane = threadIdx.x;
    unsigned hi = 0;
    #pragma unroll
    for (int i = 0; i < 4; ++i)
        hi |= (unsigned)((unsigned long long)p[lane * 4 + i] >> 32);
    unsigned any = __ballot_sync(0xffffffffu, hi != 0);
    if (lane == 0) g_is64 = (any == 0);
}

// ---------------- kernel 0a: zero counters ------------------------------------
__global__ void k_zero() {
    int i = blockIdx.x * 256 + threadIdx.x;
    if (i < N_NODES) g_cnt[i] = 0;
}

// ---------------- kernel 0b: pack edges + histogram dst -----------------------
__global__ void k_pack(const void* __restrict__ ei) {
    int e = blockIdx.x * 256 + threadIdx.x;
    if (e >= N_EDGES) return;
    int src, dst;
    if (g_is64) {
        src = (int)((const long long*)ei)[e];
        dst = (int)((const long long*)ei)[N_EDGES + e];
    } else {
        src = ((const int*)ei)[e];
        dst = ((const int*)ei)[N_EDGES + e];
    }
    src = clampN(src); dst = clampN(dst);
    g_edges[e] = make_int2(src, dst);
    atomicAdd(&g_cnt[dst], 1);
}

// ---------------- scan stage 1: per-block exclusive scan -----------------------
__global__ void __launch_bounds__(SCAN_B) k_scan1() {
    __shared__ int wsum[32];
    int t = threadIdx.x;
    int i = blockIdx.x * SCAN_B + t;
    int v = (i < N_NODES) ? g_cnt[i] : 0;

    int lane = t & 31, warp = t >> 5;
    // warp inclusive scan
    int s = v;
    #pragma unroll
    for (int off = 1; off < 32; off <<= 1) {
        int u = __shfl_up_sync(0xffffffffu, s, off);
        if (lane >= off) s += u;
    }
    if (lane == 31) wsum[warp] = s;
    __syncthreads();
    if (warp == 0) {
        int ws = (lane < 32) ? wsum[lane] : 0;
        #pragma unroll
        for (int off = 1; off < 32; off <<= 1) {
            int u = __shfl_up_sync(0xffffffffu, ws, off);
            if (lane >= off) ws += u;
        }
        wsum[lane] = ws;
    }
    __syncthreads();
    int base = warp ? wsum[warp - 1] : 0;
    int excl = base + s - v;                  // exclusive within block
    if (i < N_NODES) g_off[i] = excl;
    if (t == SCAN_B - 1) g_bsum[blockIdx.x] = base + s;  // block total
}

// ---------------- scan stage 2: scan the 49 block totals -----------------------
__global__ void k_scan2() {
    __shared__ int sm[N_SCAN_BLOCKS];
    int t = threadIdx.x;
    if (t < N_SCAN_BLOCKS) sm[t] = g_bsum[t];
    __syncthreads();
    if (t == 0) {
        int run = 0;
        for (int i = 0; i < N_SCAN_BLOCKS; ++i) {
            int c = sm[i]; sm[i] = run; run += c;
        }
        g_off[N_NODES] = N_EDGES;
    }
    __syncthreads();
    if (t < N_SCAN_BLOCKS) g_bsum[t] = sm[t];
}

// ---------------- scan stage 3: add block bases + seed cursors ------------------
__global__ void __launch_bounds__(SCAN_B) k_scan3() {
    int i = blockIdx.x * SCAN_B + threadIdx.x;
    if (i < N_NODES) {
        int o = g_off[i] + g_bsum[blockIdx.x];
        g_off[i] = o;
        g_fill[i] = o;
    }
}

// ---------------- kernel 0d: scatter src into CSR slots ------------------------
__global__ void k_scatter() {
    int e = blockIdx.x * 256 + threadIdx.x;
    if (e >= N_EDGES) return;
    int2 ed = g_edges[e];
    int pos = atomicAdd(&g_fill[ed.y], 1);
    g_csr_src[pos] = ed.x;
}

// ---------------- kernel 1: transpose W ---------------------------------------
__global__ void k_transpose(const float* __restrict__ W) {
    int i = blockIdx.x * 256 + threadIdx.x;
    if (i < HF * IN_F) {
        int j = i / IN_F, k = i % IN_F;
        g_Wt[k * HF + j] = W[i];
    }
}

// ---------------- kernel 2: h = x @ W^T  + alpha epilogue ----------------------
__global__ void __launch_bounds__(256) k_gemm(const float* __restrict__ x,
                                              const float* __restrict__ a_src,
                                              const float* __restrict__ a_dst) {
    __shared__ float xsT[IN_F][65];
    __shared__ float sA[HF], sB[HF];

    int tid = threadIdx.x;
    if (tid < HF) { sA[tid] = a_src[tid]; sB[tid] = a_dst[tid]; }

    int n0 = blockIdx.x * 64;

    #pragma unroll
    for (int it = 0; it < 8; ++it) {
        int flat = tid + it * 256;
        int n  = flat >> 5;
        int kq = flat & 31;
        float4 v = make_float4(0.f, 0.f, 0.f, 0.f);
        int gn = n0 + n;
        if (gn < N_NODES) v = *(const float4*)&x[(size_t)gn * IN_F + kq * 4];
        xsT[kq * 4 + 0][n] = v.x;
        xsT[kq * 4 + 1][n] = v.y;
        xsT[kq * 4 + 2][n] = v.z;
        xsT[kq * 4 + 3][n] = v.w;
    }
    __syncthreads();

    int jq = tid & 31;  int j0 = jq * 4;
    int ng = tid >> 5;  int nb = ng * 8;

    float4 acc[8];
    #pragma unroll
    for (int i = 0; i < 8; ++i) acc[i] = make_float4(0.f, 0.f, 0.f, 0.f);

    #pragma unroll 4
    for (int k = 0; k < IN_F; ++k) {
        float4 wv = *(const float4*)&g_Wt[k * HF + j0];
        #pragma unroll
        for (int i = 0; i < 8; ++i) {
            float xv = xsT[k][nb + i];
            acc[i].x += wv.x * xv;
            acc[i].y += wv.y * xv;
            acc[i].z += wv.z * xv;
            acc[i].w += wv.w * xv;
        }
    }

    int head = jq >> 3;
    #pragma unroll
    for (int i = 0; i < 8; ++i) {
        int gn = n0 + nb + i;
        bool ok = gn < N_NODES;
        if (ok) *(float4*)&g_h[(size_t)gn * HF + j0] = acc[i];
        float s1 = acc[i].x * sA[j0] + acc[i].y * sA[j0 + 1] +
                   acc[i].z * sA[j0 + 2] + acc[i].w * sA[j0 + 3];
        float s2 = acc[i].x * sB[j0] + acc[i].y * sB[j0 + 1] +
                   acc[i].z * sB[j0 + 2] + acc[i].w * sB[j0 + 3];
        #pragma unroll
        for (int off = 1; off < 8; off <<= 1) {
            s1 += __shfl_xor_sync(0xffffffffu, s1, off);
            s2 += __shfl_xor_sync(0xffffffffu, s2, off);
        }
        if (ok && (jq & 7) == 0) {
            g_asrc[gn * HEADS + head] = s1;
            g_adst[gn * HEADS + head] = s2;
        }
    }
}

// ---------------- kernel 3: CSR aggregation (warp per dst node) ----------------
#define CHUNK 64
__global__ void __launch_bounds__(256) k_agg(float* __restrict__ out) {
    __shared__ float4 sh_exp[8][CHUNK];
    __shared__ int    sh_src[8][CHUNK];

    int w    = threadIdx.x >> 5;
    int lane = threadIdx.x & 31;
    int n    = blockIdx.x * 8 + w;
    if (n >= N_NODES) return;

    int start = g_off[n];
    int end   = g_off[n + 1];

    float4 acc = make_float4(0.f, 0.f, 0.f, 0.f);
    float4 sum = make_float4(0.f, 0.f, 0.f, 0.f);
    int head = lane >> 3;

    if (start < end) {
        float4 b4 = *(const float4*)&g_adst[n * HEADS];

        for (int cs = start; cs < end; cs += CHUNK) {
            int cnt = min(end - cs, CHUNK);
            for (int k = lane; k < cnt; k += 32) {
                int src = g_csr_src[cs + k];
                float4 a = *(const float4*)&g_asrc[src * HEADS];
                float v0 = a.x + b4.x, v1 = a.y + b4.y;
                float v2 = a.z + b4.z, v3 = a.w + b4.w;
                v0 = v0 > 0.f ? v0 : NEG_SLOPE * v0;
                v1 = v1 > 0.f ? v1 : NEG_SLOPE * v1;
                v2 = v2 > 0.f ? v2 : NEG_SLOPE * v2;
                v3 = v3 > 0.f ? v3 : NEG_SLOPE * v3;
                float4 ex = make_float4(__expf(v0), __expf(v1), __expf(v2), __expf(v3));
                sh_exp[w][k] = ex;
                sh_src[w][k] = src;
                sum.x += ex.x; sum.y += ex.y; sum.z += ex.z; sum.w += ex.w;
            }
            __syncwarp();
            #pragma unroll 4
            for (int k = 0; k < cnt; ++k) {
                int src = sh_src[w][k];
                float att = ((const float*)&sh_exp[w][k])[head];
                float4 hv = *(const float4*)&g_h[(size_t)src * HF + lane * 4];
                acc.x += att * hv.x;
                acc.y += att * hv.y;
                acc.z += att * hv.z;
                acc.w += att * hv.w;
            }
            __syncwarp();
        }

        #pragma unroll
        for (int off = 1; off < 32; off <<= 1) {
            sum.x += __shfl_xor_sync(0xffffffffu, sum.x, off);
            sum.y += __shfl_xor_sync(0xffffffffu, sum.y, off);
            sum.z += __shfl_xor_sync(0xffffffffu, sum.z, off);
            sum.w += __shfl_xor_sync(0xffffffffu, sum.w, off);
        }
        float sh = ((const float*)&sum)[head];
        float inv = 1.f / (sh + EPSF);
        acc.x *= inv; acc.y *= inv; acc.z *= inv; acc.w *= inv;
    }
    *(float4*)&out[(size_t)n * HF + lane * 4] = acc;
}

// ---------------- launch -------------------------------------------------------
extern "C" void kernel_launch(void* const* d_in, const int* in_sizes, int n_in,
                              void* d_out, int out_size) {
    const float* x     = (const float*)d_in[0];
    const void*  ei    = d_in[1];
    const float* W     = (const float*)d_in[2];
    const float* a_src = (const float*)d_in[3];
    const float* a_dst = (const float*)d_in[4];
    float*       out   = (float*)d_out;

    k_detect<<<1, 32>>>(ei);
    k_zero<<<(N_NODES + 255) / 256, 256>>>();
    k_pack<<<(N_EDGES + 255) / 256, 256>>>(ei);
    k_scan1<<<N_SCAN_BLOCKS, SCAN_B>>>();
    k_scan2<<<1, 64>>>();
    k_scan3<<<N_SCAN_BLOCKS, SCAN_B>>>();
    k_scatter<<<(N_EDGES + 255) / 256, 256>>>();
    k_transpose<<<(HF * IN_F + 255) / 256, 256>>>(W);
    k_gemm<<<(N_NODES + 63) / 64, 256>>>(x, a_src, a_dst);
    k_agg<<<(N_NODES + 7) / 8, 256>>>(out);
}

// round 9
// speedup vs baseline: 1.8905x; 1.1022x over previous
#include <cuda_runtime.h>
#include <math_constants.h>

#define N_NODES 50000
#define N_EDGES 800000
#define IN_F 128
#define HF    128   // HEADS * OUT_F
#define HEADS 4
#define NEG_SLOPE 0.2f
#define EPSF 1e-8f

#define SCAN_B 1024
#define N_SCAN_BLOCKS ((N_NODES + SCAN_B - 1) / SCAN_B)   // 49

// ---------------- scratch (static device globals; no allocations) -------------
__device__ __align__(16) float g_h[N_NODES * HF];        // 25.6 MB
__device__ float  g_Wt[IN_F * HF];                        // W transposed (k-major)
__device__ __align__(16) float g_asrc[N_NODES * HEADS];
__device__ __align__(16) float g_adst[N_NODES * HEADS];
__device__ __align__(8) int2 g_edges[N_EDGES];            // packed (src,dst)
__device__ int  g_cnt[N_NODES];                           // per-dst degree
__device__ int  g_fill[N_NODES];                          // scatter cursors
__device__ int  g_off[N_NODES + 1];                       // CSR offsets
__device__ int  g_bsum[N_SCAN_BLOCKS];                    // per-block totals
__device__ int  g_csr_src[N_EDGES];                       // src sorted by dst
__device__ int  g_is64;                                   // dtype flag

__device__ __forceinline__ int clampN(int v) {
    v = v < 0 ? 0 : v;
    return v >= N_NODES ? N_NODES - 1 : v;
}

// ---------------- kernel 0: zero counters + dtype detect (block 0) -------------
__global__ void k_zero_detect(const void* __restrict__ ei) {
    int i = blockIdx.x * 256 + threadIdx.x;
    if (i < N_NODES) g_cnt[i] = 0;
    if (blockIdx.x == 0 && threadIdx.x < 32) {
        const long long* p = (const long long*)ei;
        int lane = threadIdx.x;
        unsigned hi = 0;
        #pragma unroll
        for (int k = 0; k < 4; ++k)
            hi |= (unsigned)((unsigned long long)p[lane * 4 + k] >> 32);
        unsigned any = __ballot_sync(0xffffffffu, hi != 0);
        if (lane == 0) g_is64 = (any == 0);
    }
}

// ---------------- kernel 0b: pack edges + histogram dst -----------------------
__global__ void k_pack(const void* __restrict__ ei) {
    int e = blockIdx.x * 256 + threadIdx.x;
    if (e >= N_EDGES) return;
    int src, dst;
    if (g_is64) {
        src = (int)((const long long*)ei)[e];
        dst = (int)((const long long*)ei)[N_EDGES + e];
    } else {
        src = ((const int*)ei)[e];
        dst = ((const int*)ei)[N_EDGES + e];
    }
    src = clampN(src); dst = clampN(dst);
    g_edges[e] = make_int2(src, dst);
    atomicAdd(&g_cnt[dst], 1);
}

// ---------------- scan stage 1: per-block exclusive scan -----------------------
__global__ void __launch_bounds__(SCAN_B) k_scan1() {
    __shared__ int wsum[32];
    int t = threadIdx.x;
    int i = blockIdx.x * SCAN_B + t;
    int v = (i < N_NODES) ? g_cnt[i] : 0;

    int lane = t & 31, warp = t >> 5;
    int s = v;
    #pragma unroll
    for (int off = 1; off < 32; off <<= 1) {
        int u = __shfl_up_sync(0xffffffffu, s, off);
        if (lane >= off) s += u;
    }
    if (lane == 31) wsum[warp] = s;
    __syncthreads();
    if (warp == 0) {
        int ws = wsum[lane];
        #pragma unroll
        for (int off = 1; off < 32; off <<= 1) {
            int u = __shfl_up_sync(0xffffffffu, ws, off);
            if (lane >= off) ws += u;
        }
        wsum[lane] = ws;
    }
    __syncthreads();
    int base = warp ? wsum[warp - 1] : 0;
    int excl = base + s - v;
    if (i < N_NODES) g_off[i] = excl;
    if (t == SCAN_B - 1) g_bsum[blockIdx.x] = base + s;
}

// ---------------- scan stage 2: scan the 49 block totals -----------------------
__global__ void k_scan2() {
    __shared__ int sm[N_SCAN_BLOCKS];
    int t = threadIdx.x;
    if (t < N_SCAN_BLOCKS) sm[t] = g_bsum[t];
    __syncthreads();
    if (t == 0) {
        int run = 0;
        for (int i = 0; i < N_SCAN_BLOCKS; ++i) {
            int c = sm[i]; sm[i] = run; run += c;
        }
        g_off[N_NODES] = N_EDGES;
    }
    __syncthreads();
    if (t < N_SCAN_BLOCKS) g_bsum[t] = sm[t];
}

// ---------------- scan stage 3: add block bases + seed cursors ------------------
__global__ void __launch_bounds__(SCAN_B) k_scan3() {
    int i = blockIdx.x * SCAN_B + threadIdx.x;
    if (i < N_NODES) {
        int o = g_off[i] + g_bsum[blockIdx.x];
        g_off[i] = o;
        g_fill[i] = o;
    }
}

// ---------------- kernel 0d: scatter src into CSR slots ------------------------
__global__ void k_scatter() {
    int e = blockIdx.x * 256 + threadIdx.x;
    if (e >= N_EDGES) return;
    int2 ed = g_edges[e];
    int pos = atomicAdd(&g_fill[ed.y], 1);
    g_csr_src[pos] = ed.x;
}

// ---------------- kernel 1: transpose W ---------------------------------------
__global__ void k_transpose(const float* __restrict__ W) {
    int i = blockIdx.x * 256 + threadIdx.x;
    if (i < HF * IN_F) {
        int j = i / IN_F, k = i % IN_F;
        g_Wt[k * HF + j] = W[i];
    }
}

// ---------------- kernel 2: h = x @ W^T  + alpha epilogue ----------------------
__global__ void __launch_bounds__(256) k_gemm(const float* __restrict__ x,
                                              const float* __restrict__ a_src,
                                              const float* __restrict__ a_dst) {
    __shared__ float xsT[IN_F][65];
    __shared__ float sA[HF], sB[HF];

    int tid = threadIdx.x;
    if (tid < HF) { sA[tid] = a_src[tid]; sB[tid] = a_dst[tid]; }

    int n0 = blockIdx.x * 64;

    #pragma unroll
    for (int it = 0; it < 8; ++it) {
        int flat = tid + it * 256;
        int n  = flat >> 5;
        int kq = flat & 31;
        float4 v = make_float4(0.f, 0.f, 0.f, 0.f);
        int gn = n0 + n;
        if (gn < N_NODES) v = *(const float4*)&x[(size_t)gn * IN_F + kq * 4];
        xsT[kq * 4 + 0][n] = v.x;
        xsT[kq * 4 + 1][n] = v.y;
        xsT[kq * 4 + 2][n] = v.z;
        xsT[kq * 4 + 3][n] = v.w;
    }
    __syncthreads();

    int jq = tid & 31;  int j0 = jq * 4;
    int ng = tid >> 5;  int nb = ng * 8;

    float4 acc[8];
    #pragma unroll
    for (int i = 0; i < 8; ++i) acc[i] = make_float4(0.f, 0.f, 0.f, 0.f);

    #pragma unroll 4
    for (int k = 0; k < IN_F; ++k) {
        float4 wv = *(const float4*)&g_Wt[k * HF + j0];
        #pragma unroll
        for (int i = 0; i < 8; ++i) {
            float xv = xsT[k][nb + i];
            acc[i].x += wv.x * xv;
            acc[i].y += wv.y * xv;
            acc[i].z += wv.z * xv;
            acc[i].w += wv.w * xv;
        }
    }

    int head = jq >> 3;
    #pragma unroll
    for (int i = 0; i < 8; ++i) {
        int gn = n0 + nb + i;
        bool ok = gn < N_NODES;
        if (ok) *(float4*)&g_h[(size_t)gn * HF + j0] = acc[i];
        float s1 = acc[i].x * sA[j0] + acc[i].y * sA[j0 + 1] +
                   acc[i].z * sA[j0 + 2] + acc[i].w * sA[j0 + 3];
        float s2 = acc[i].x * sB[j0] + acc[i].y * sB[j0 + 1] +
                   acc[i].z * sB[j0 + 2] + acc[i].w * sB[j0 + 3];
        #pragma unroll
        for (int off = 1; off < 8; off <<= 1) {
            s1 += __shfl_xor_sync(0xffffffffu, s1, off);
            s2 += __shfl_xor_sync(0xffffffffu, s2, off);
        }
        if (ok && (jq & 7) == 0) {
            g_asrc[gn * HEADS + head] = s1;
            g_adst[gn * HEADS + head] = s2;
        }
    }
}

// ---------------- kernel 3: CSR aggregation (warp per dst node) ----------------
#define CHUNK 64
__global__ void __launch_bounds__(256) k_agg(float* __restrict__ out) {
    __shared__ float4 sh_exp[8][CHUNK];
    __shared__ int    sh_src[8][CHUNK];

    int w    = threadIdx.x >> 5;
    int lane = threadIdx.x & 31;
    int n    = blockIdx.x * 8 + w;
    if (n >= N_NODES) return;

    int start = g_off[n];
    int end   = g_off[n + 1];

    float4 acc = make_float4(0.f, 0.f, 0.f, 0.f);
    float4 sum = make_float4(0.f, 0.f, 0.f, 0.f);
    int head = lane >> 3;

    if (start < end) {
        float4 b4 = *(const float4*)&g_adst[n * HEADS];

        for (int cs = start; cs < end; cs += CHUNK) {
            int cnt = min(end - cs, CHUNK);
            for (int k = lane; k < cnt; k += 32) {
                int src = g_csr_src[cs + k];
                float4 a = *(const float4*)&g_asrc[src * HEADS];
                float v0 = a.x + b4.x, v1 = a.y + b4.y;
                float v2 = a.z + b4.z, v3 = a.w + b4.w;
                v0 = v0 > 0.f ? v0 : NEG_SLOPE * v0;
                v1 = v1 > 0.f ? v1 : NEG_SLOPE * v1;
                v2 = v2 > 0.f ? v2 : NEG_SLOPE * v2;
                v3 = v3 > 0.f ? v3 : NEG_SLOPE * v3;
                float4 ex = make_float4(__expf(v0), __expf(v1), __expf(v2), __expf(v3));
                sh_exp[w][k] = ex;
                sh_src[w][k] = src;
                sum.x += ex.x; sum.y += ex.y; sum.z += ex.z; sum.w += ex.w;
            }
            __syncwarp();
            #pragma unroll 8
            for (int k = 0; k < cnt; ++k) {
                int src = sh_src[w][k];
                float att = ((const float*)&sh_exp[w][k])[head];
                float4 hv = *(const float4*)&g_h[(size_t)src * HF + lane * 4];
                acc.x += att * hv.x;
                acc.y += att * hv.y;
                acc.z += att * hv.z;
                acc.w += att * hv.w;
            }
            __syncwarp();
        }

        #pragma unroll
        for (int off = 1; off < 32; off <<= 1) {
            sum.x += __shfl_xor_sync(0xffffffffu, sum.x, off);
            sum.y += __shfl_xor_sync(0xffffffffu, sum.y, off);
            sum.z += __shfl_xor_sync(0xffffffffu, sum.z, off);
            sum.w += __shfl_xor_sync(0xffffffffu, sum.w, off);
        }
        float sh = ((const float*)&sum)[head];
        float inv = 1.f / (sh + EPSF);
        acc.x *= inv; acc.y *= inv; acc.z *= inv; acc.w *= inv;
    }
    *(float4*)&out[(size_t)n * HF + lane * 4] = acc;
}

// ---------------- launch (fork/join two independent chains) --------------------
extern "C" void kernel_launch(void* const* d_in, const int* in_sizes, int n_in,
                              void* d_out, int out_size) {
    const float* x     = (const float*)d_in[0];
    const void*  ei    = d_in[1];
    const float* W     = (const float*)d_in[2];
    const float* a_src = (const float*)d_in[3];
    const float* a_dst = (const float*)d_in[4];
    float*       out   = (float*)d_out;

    static cudaStream_t sA = nullptr;
    static cudaEvent_t  evFork = nullptr, evJoin = nullptr;
    if (!sA) {
        cudaStreamCreateWithFlags(&sA, cudaStreamNonBlocking);
        cudaEventCreateWithFlags(&evFork, cudaEventDisableTiming);
        cudaEventCreateWithFlags(&evJoin, cudaEventDisableTiming);
    }

    // fork: branch A (CSR build) on sA, branch B (transpose+gemm) on stream 0
    cudaEventRecord(evFork, 0);
    cudaStreamWaitEvent(sA, evFork, 0);

    // branch A: CSR build
    k_zero_detect<<<(N_NODES + 255) / 256, 256, 0, sA>>>(ei);
    k_pack<<<(N_EDGES + 255) / 256, 256, 0, sA>>>(ei);
    k_scan1<<<N_SCAN_BLOCKS, SCAN_B, 0, sA>>>();
    k_scan2<<<1, 64, 0, sA>>>();
    k_scan3<<<N_SCAN_BLOCKS, SCAN_B, 0, sA>>>();
    k_scatter<<<(N_EDGES + 255) / 256, 256, 0, sA>>>();
    cudaEventRecord(evJoin, sA);

    // branch B: feature transform
    k_transpose<<<(HF * IN_F + 255) / 256, 256>>>(W);
    k_gemm<<<(N_NODES + 63) / 64, 256>>>(x, a_src, a_dst);

    // join, then aggregate
    cudaStreamWaitEvent(0, evJoin, 0);
    k_agg<<<(N_NODES + 7) / 8, 256>>>(out);
}

// round 10
// speedup vs baseline: 1.9982x; 1.0570x over previous
#include <cuda_runtime.h>
#include <cuda_fp16.h>
#include <math_constants.h>

#define N_NODES 50000
#define N_EDGES 800000
#define IN_F 128
#define HF    128   // HEADS * OUT_F
#define HEADS 4
#define NEG_SLOPE 0.2f
#define EPSF 1e-8f

#define SCAN_B 1024
#define N_SCAN_BLOCKS ((N_NODES + SCAN_B - 1) / SCAN_B)   // 49

// ---------------- scratch (static device globals; no allocations) -------------
__device__ __align__(16) __half g_h[N_NODES * HF];        // 12.8 MB (fp16)
__device__ float  g_Wt[IN_F * HF];                        // W transposed (k-major)
__device__ __align__(16) float g_asrc[N_NODES * HEADS];
__device__ __align__(16) float g_adst[N_NODES * HEADS];
__device__ __align__(8) int2 g_edges[N_EDGES];            // packed (src,dst)
__device__ int  g_cnt[N_NODES];                           // per-dst degree
__device__ int  g_fill[N_NODES];                          // scatter cursors
__device__ int  g_off[N_NODES + 1];                       // CSR offsets
__device__ int  g_bsum[N_SCAN_BLOCKS];                    // per-block totals
__device__ int  g_csr_src[N_EDGES];                       // src sorted by dst
__device__ int  g_is64;                                   // dtype flag

__device__ __forceinline__ int clampN(int v) {
    v = v < 0 ? 0 : v;
    return v >= N_NODES ? N_NODES - 1 : v;
}

// ---------------- kernel 0: zero counters + dtype detect (block 0) -------------
__global__ void k_zero_detect(const void* __restrict__ ei) {
    int i = blockIdx.x * 256 + threadIdx.x;
    if (i < N_NODES) g_cnt[i] = 0;
    if (blockIdx.x == 0 && threadIdx.x < 32) {
        const long long* p = (const long long*)ei;
        int lane = threadIdx.x;
        unsigned hi = 0;
        #pragma unroll
        for (int k = 0; k < 4; ++k)
            hi |= (unsigned)((unsigned long long)p[lane * 4 + k] >> 32);
        unsigned any = __ballot_sync(0xffffffffu, hi != 0);
        if (lane == 0) g_is64 = (any == 0);
    }
}

// ---------------- kernel 0b: pack edges + histogram dst -----------------------
__global__ void k_pack(const void* __restrict__ ei) {
    int e = blockIdx.x * 256 + threadIdx.x;
    if (e >= N_EDGES) return;
    int src, dst;
    if (g_is64) {
        src = (int)((const long long*)ei)[e];
        dst = (int)((const long long*)ei)[N_EDGES + e];
    } else {
        src = ((const int*)ei)[e];
        dst = ((const int*)ei)[N_EDGES + e];
    }
    src = clampN(src); dst = clampN(dst);
    g_edges[e] = make_int2(src, dst);
    atomicAdd(&g_cnt[dst], 1);
}

// ---------------- scan stage 1: per-block exclusive scan -----------------------
__global__ void __launch_bounds__(SCAN_B) k_scan1() {
    __shared__ int wsum[32];
    int t = threadIdx.x;
    int i = blockIdx.x * SCAN_B + t;
    int v = (i < N_NODES) ? g_cnt[i] : 0;

    int lane = t & 31, warp = t >> 5;
    int s = v;
    #pragma unroll
    for (int off = 1; off < 32; off <<= 1) {
        int u = __shfl_up_sync(0xffffffffu, s, off);
        if (lane >= off) s += u;
    }
    if (lane == 31) wsum[warp] = s;
    __syncthreads();
    if (warp == 0) {
        int ws = wsum[lane];
        #pragma unroll
        for (int off = 1; off < 32; off <<= 1) {
            int u = __shfl_up_sync(0xffffffffu, ws, off);
            if (lane >= off) ws += u;
        }
        wsum[lane] = ws;
    }
    __syncthreads();
    int base = warp ? wsum[warp - 1] : 0;
    int excl = base + s - v;
    if (i < N_NODES) g_off[i] = excl;
    if (t == SCAN_B - 1) g_bsum[blockIdx.x] = base + s;
}

// ---------------- scan stage 2: scan the 49 block totals -----------------------
__global__ void k_scan2() {
    __shared__ int sm[N_SCAN_BLOCKS];
    int t = threadIdx.x;
    if (t < N_SCAN_BLOCKS) sm[t] = g_bsum[t];
    __syncthreads();
    if (t == 0) {
        int run = 0;
        for (int i = 0; i < N_SCAN_BLOCKS; ++i) {
            int c = sm[i]; sm[i] = run; run += c;
        }
        g_off[N_NODES] = N_EDGES;
    }
    __syncthreads();
    if (t < N_SCAN_BLOCKS) g_bsum[t] = sm[t];
}

// ---------------- scan stage 3: add block bases + seed cursors ------------------
__global__ void __launch_bounds__(SCAN_B) k_scan3() {
    int i = blockIdx.x * SCAN_B + threadIdx.x;
    if (i < N_NODES) {
        int o = g_off[i] + g_bsum[blockIdx.x];
        g_off[i] = o;
        g_fill[i] = o;
    }
}

// ---------------- kernel 0d: scatter src into CSR slots ------------------------
__global__ void k_scatter() {
    int e = blockIdx.x * 256 + threadIdx.x;
    if (e >= N_EDGES) return;
    int2 ed = g_edges[e];
    int pos = atomicAdd(&g_fill[ed.y], 1);
    g_csr_src[pos] = ed.x;
}

// ---------------- kernel 1: transpose W ---------------------------------------
__global__ void k_transpose(const float* __restrict__ W) {
    int i = blockIdx.x * 256 + threadIdx.x;
    if (i < HF * IN_F) {
        int j = i / IN_F, k = i % IN_F;
        g_Wt[k * HF + j] = W[i];
    }
}

// ---------------- kernel 2: h = x @ W^T  + alpha epilogue ----------------------
// h stored fp16; alphas computed from fp32 accumulators (full precision).
__global__ void __launch_bounds__(256) k_gemm(const float* __restrict__ x,
                                              const float* __restrict__ a_src,
                                              const float* __restrict__ a_dst) {
    __shared__ float xsT[IN_F][65];
    __shared__ float sA[HF], sB[HF];

    int tid = threadIdx.x;
    if (tid < HF) { sA[tid] = a_src[tid]; sB[tid] = a_dst[tid]; }

    int n0 = blockIdx.x * 64;

    #pragma unroll
    for (int it = 0; it < 8; ++it) {
        int flat = tid + it * 256;
        int n  = flat >> 5;
        int kq = flat & 31;
        float4 v = make_float4(0.f, 0.f, 0.f, 0.f);
        int gn = n0 + n;
        if (gn < N_NODES) v = *(const float4*)&x[(size_t)gn * IN_F + kq * 4];
        xsT[kq * 4 + 0][n] = v.x;
        xsT[kq * 4 + 1][n] = v.y;
        xsT[kq * 4 + 2][n] = v.z;
        xsT[kq * 4 + 3][n] = v.w;
    }
    __syncthreads();

    int jq = tid & 31;  int j0 = jq * 4;
    int ng = tid >> 5;  int nb = ng * 8;

    float4 acc[8];
    #pragma unroll
    for (int i = 0; i < 8; ++i) acc[i] = make_float4(0.f, 0.f, 0.f, 0.f);

    #pragma unroll 4
    for (int k = 0; k < IN_F; ++k) {
        float4 wv = *(const float4*)&g_Wt[k * HF + j0];
        #pragma unroll
        for (int i = 0; i < 8; ++i) {
            float xv = xsT[k][nb + i];
            acc[i].x += wv.x * xv;
            acc[i].y += wv.y * xv;
            acc[i].z += wv.z * xv;
            acc[i].w += wv.w * xv;
        }
    }

    int head = jq >> 3;
    #pragma unroll
    for (int i = 0; i < 8; ++i) {
        int gn = n0 + nb + i;
        bool ok = gn < N_NODES;
        if (ok) {
            __half2 h01 = __floats2half2_rn(acc[i].x, acc[i].y);
            __half2 h23 = __floats2half2_rn(acc[i].z, acc[i].w);
            uint2 pk = make_uint2(*(unsigned*)&h01, *(unsigned*)&h23);
            *(uint2*)&g_h[(size_t)gn * HF + j0] = pk;
        }
        float s1 = acc[i].x * sA[j0] + acc[i].y * sA[j0 + 1] +
                   acc[i].z * sA[j0 + 2] + acc[i].w * sA[j0 + 3];
        float s2 = acc[i].x * sB[j0] + acc[i].y * sB[j0 + 1] +
                   acc[i].z * sB[j0 + 2] + acc[i].w * sB[j0 + 3];
        #pragma unroll
        for (int off = 1; off < 8; off <<= 1) {
            s1 += __shfl_xor_sync(0xffffffffu, s1, off);
            s2 += __shfl_xor_sync(0xffffffffu, s2, off);
        }
        if (ok && (jq & 7) == 0) {
            g_asrc[gn * HEADS + head] = s1;
            g_adst[gn * HEADS + head] = s2;
        }
    }
}

// ---------------- kernel 3: CSR aggregation (warp per dst node) ----------------
#define CHUNK 64
__global__ void __launch_bounds__(256) k_agg(float* __restrict__ out) {
    __shared__ float4 sh_exp[8][CHUNK];
    __shared__ int    sh_src[8][CHUNK];

    int w    = threadIdx.x >> 5;
    int lane = threadIdx.x & 31;
    int n    = blockIdx.x * 8 + w;
    if (n >= N_NODES) return;

    int start = g_off[n];
    int end   = g_off[n + 1];

    float4 acc = make_float4(0.f, 0.f, 0.f, 0.f);
    float4 sum = make_float4(0.f, 0.f, 0.f, 0.f);
    int head = lane >> 3;

    if (start < end) {
        float4 b4 = *(const float4*)&g_adst[n * HEADS];

        for (int cs = start; cs < end; cs += CHUNK) {
            int cnt = min(end - cs, CHUNK);
            for (int k = lane; k < cnt; k += 32) {
                int src = g_csr_src[cs + k];
                float4 a = *(const float4*)&g_asrc[src * HEADS];
                float v0 = a.x + b4.x, v1 = a.y + b4.y;
                float v2 = a.z + b4.z, v3 = a.w + b4.w;
                v0 = v0 > 0.f ? v0 : NEG_SLOPE * v0;
                v1 = v1 > 0.f ? v1 : NEG_SLOPE * v1;
                v2 = v2 > 0.f ? v2 : NEG_SLOPE * v2;
                v3 = v3 > 0.f ? v3 : NEG_SLOPE * v3;
                float4 ex = make_float4(__expf(v0), __expf(v1), __expf(v2), __expf(v3));
                sh_exp[w][k] = ex;
                sh_src[w][k] = src;
                sum.x += ex.x; sum.y += ex.y; sum.z += ex.z; sum.w += ex.w;
            }
            __syncwarp();
            #pragma unroll 8
            for (int k = 0; k < cnt; ++k) {
                int src = sh_src[w][k];
                float att = ((const float*)&sh_exp[w][k])[head];
                uint2 pk = *(const uint2*)&g_h[(size_t)src * HF + lane * 4];
                float2 f01 = __half22float2(*(__half2*)&pk.x);
                float2 f23 = __half22float2(*(__half2*)&pk.y);
                acc.x += att * f01.x;
                acc.y += att * f01.y;
                acc.z += att * f23.x;
                acc.w += att * f23.y;
            }
            __syncwarp();
        }

        #pragma unroll
        for (int off = 1; off < 32; off <<= 1) {
            sum.x += __shfl_xor_sync(0xffffffffu, sum.x, off);
            sum.y += __shfl_xor_sync(0xffffffffu, sum.y, off);
            sum.z += __shfl_xor_sync(0xffffffffu, sum.z, off);
            sum.w += __shfl_xor_sync(0xffffffffu, sum.w, off);
        }
        float sh = ((const float*)&sum)[head];
        float inv = 1.f / (sh + EPSF);
        acc.x *= inv; acc.y *= inv; acc.z *= inv; acc.w *= inv;
    }
    *(float4*)&out[(size_t)n * HF + lane * 4] = acc;
}

// ---------------- launch (fork/join two independent chains) --------------------
extern "C" void kernel_launch(void* const* d_in, const int* in_sizes, int n_in,
                              void* d_out, int out_size) {
    const float* x     = (const float*)d_in[0];
    const void*  ei    = d_in[1];
    const float* W     = (const float*)d_in[2];
    const float* a_src = (const float*)d_in[3];
    const float* a_dst = (const float*)d_in[4];
    float*       out   = (float*)d_out;

    static cudaStream_t sA = nullptr;
    static cudaEvent_t  evFork = nullptr, evJoin = nullptr;
    if (!sA) {
        cudaStreamCreateWithFlags(&sA, cudaStreamNonBlocking);
        cudaEventCreateWithFlags(&evFork, cudaEventDisableTiming);
        cudaEventCreateWithFlags(&evJoin, cudaEventDisableTiming);
    }

    // fork: branch A (CSR build) on sA, branch B (transpose+gemm) on stream 0
    cudaEventRecord(evFork, 0);
    cudaStreamWaitEvent(sA, evFork, 0);

    // branch A: CSR build
    k_zero_detect<<<(N_NODES + 255) / 256, 256, 0, sA>>>(ei);
    k_pack<<<(N_EDGES + 255) / 256, 256, 0, sA>>>(ei);
    k_scan1<<<N_SCAN_BLOCKS, SCAN_B, 0, sA>>>();
    k_scan2<<<1, 64, 0, sA>>>();
    k_scan3<<<N_SCAN_BLOCKS, SCAN_B, 0, sA>>>();
    k_scatter<<<(N_EDGES + 255) / 256, 256, 0, sA>>>();
    cudaEventRecord(evJoin, sA);

    // branch B: feature transform
    k_transpose<<<(HF * IN_F + 255) / 256, 256>>>(W);
    k_gemm<<<(N_NODES + 63) / 64, 256>>>(x, a_src, a_dst);

    // join, then aggregate
    cudaStreamWaitEvent(0, evJoin, 0);
    k_agg<<<(N_NODES + 7) / 8, 256>>>(out);
}